// round 1
// baseline (speedup 1.0000x reference)
#include <cuda_runtime.h>
#include <cstdint>
#include <cstddef>

// Problem dims (fixed by the dataset)
#define M_DIM 4096
#define N_DIM 4096
#define K_DIM 4096
#define GROUP 128
#define G_DIM (K_DIM / GROUP)

// GEMM tiling
#define BM 128
#define BN 128
#define BK 32
#define PAD 36                      // smem row stride in floats (bank = 4*row + k -> conflict-free)
#define THREADS 256
#define SMEM_BYTES (2 * (BM * PAD + BN * PAD) * 4)   // double-buffered A+B = 73728 B

// Scratch (allocation is banned; __device__ globals are the sanctioned workaround)
__device__ float g_W[(size_t)N_DIM * K_DIM];   // dequantized, tf32-rounded weights [N,K]
__device__ float g_X[(size_t)M_DIM * K_DIM];   // tf32-rounded activations      [M,K]

// ---------------------------------------------------------------------------
// helpers
// ---------------------------------------------------------------------------
__device__ __forceinline__ float to_tf32(float x) {
    uint32_t u;
    asm("cvt.rna.tf32.f32 %0, %1;" : "=r"(u) : "f"(x));
    return __uint_as_float(u);
}

__device__ __forceinline__ void cp_async16(void* smem_ptr, const void* gptr) {
    uint32_t s = (uint32_t)__cvta_generic_to_shared(smem_ptr);
    asm volatile("cp.async.cg.shared.global [%0], [%1], 16;\n" :: "r"(s), "l"(gptr));
}
__device__ __forceinline__ void cp_commit() { asm volatile("cp.async.commit_group;\n"); }
template <int N>
__device__ __forceinline__ void cp_wait() { asm volatile("cp.async.wait_group %0;\n" :: "n"(N)); }

__device__ __forceinline__ void mma_tf32(float* c, const uint32_t* a, const uint32_t* b) {
    asm volatile(
        "mma.sync.aligned.m16n8k8.row.col.f32.tf32.tf32.f32 "
        "{%0,%1,%2,%3}, {%4,%5,%6,%7}, {%8,%9}, {%0,%1,%2,%3};\n"
        : "+f"(c[0]), "+f"(c[1]), "+f"(c[2]), "+f"(c[3])
        : "r"(a[0]), "r"(a[1]), "r"(a[2]), "r"(a[3]), "r"(b[0]), "r"(b[1]));
}

// ---------------------------------------------------------------------------
// prologue 1: x -> tf32-rounded fp32 (RNA; avoids the biased HW truncation)
// ---------------------------------------------------------------------------
__global__ void convert_x_kernel(const float4* __restrict__ x) {
    size_t i = (size_t)blockIdx.x * blockDim.x + threadIdx.x;   // float4 index
    float4 v = x[i];
    float4 o;
    o.x = to_tf32(v.x); o.y = to_tf32(v.y); o.z = to_tf32(v.z); o.w = to_tf32(v.w);
    reinterpret_cast<float4*>(g_X)[i] = o;
}

// ---------------------------------------------------------------------------
// prologue 2: LUT dequant  W[n,k] = rna(tables[q[n,k]] * scales[n, k/128])
// ---------------------------------------------------------------------------
__global__ void dequant_kernel(const int* __restrict__ qw,
                               const float* __restrict__ scales,
                               const float* __restrict__ tables) {
    __shared__ float t[16];
    if (threadIdx.x < 16) t[threadIdx.x] = tables[threadIdx.x];
    __syncthreads();

    size_t i = (size_t)blockIdx.x * blockDim.x + threadIdx.x;   // int4 index (4 elems)
    int4 q = reinterpret_cast<const int4*>(qw)[i];
    size_t e0 = i << 2;                  // element index
    int n = (int)(e0 >> 12);             // / 4096
    int k = (int)(e0 & 4095);
    float s = scales[n * G_DIM + (k >> 7)];   // group constant across the 4 elems

    float4 w;
    w.x = to_tf32(t[q.x] * s);
    w.y = to_tf32(t[q.y] * s);
    w.z = to_tf32(t[q.z] * s);
    w.w = to_tf32(t[q.w] * s);
    reinterpret_cast<float4*>(g_W)[i] = w;
}

// ---------------------------------------------------------------------------
// main GEMM: out[m,n] = sum_k g_X[m,k] * g_W[n,k]   (tf32 mma.sync, cp.async DB)
// block tile 128x128x32, 8 warps in 2(M) x 4(N) grid, warp tile 64x32
// ---------------------------------------------------------------------------
__global__ void __launch_bounds__(THREADS, 2)
gemm_tf32_kernel(float* __restrict__ out) {
    extern __shared__ float smem[];
    float* As = smem;                    // [2][BM][PAD]
    float* Bs = smem + 2 * BM * PAD;     // [2][BN][PAD]

    const int tid  = threadIdx.x;
    const int warp = tid >> 5;
    const int lane = tid & 31;
    const int wm   = warp >> 2;          // 0..1
    const int wn   = warp & 3;           // 0..3
    const int g    = lane >> 2;          // groupID (0..7)
    const int tig  = lane & 3;           // thread-in-group (0..3)

    const int bM = blockIdx.y * BM;
    const int bN = blockIdx.x * BN;

    const float* gA = g_X + (size_t)bM * K_DIM;
    const float* gB = g_W + (size_t)bN * K_DIM;

    float acc[4][4][4];
    #pragma unroll
    for (int i = 0; i < 4; i++)
        #pragma unroll
        for (int j = 0; j < 4; j++)
            #pragma unroll
            for (int r = 0; r < 4; r++) acc[i][j][r] = 0.f;

    // global->shared tile loader: 128 rows x 32 cols per operand, 4 float4/thread each
    auto load_tiles = [&](int k0, int buf) {
        #pragma unroll
        for (int j = 0; j < 4; j++) {
            int idx = tid + j * THREADS;
            int row = idx >> 3;
            int c4  = (idx & 7) << 2;
            cp_async16(&As[buf * BM * PAD + row * PAD + c4],
                       gA + (size_t)row * K_DIM + k0 + c4);
            cp_async16(&Bs[buf * BM * PAD + row * PAD + c4],
                       gB + (size_t)row * K_DIM + k0 + c4);
        }
    };

    load_tiles(0, 0);
    cp_commit();

    const int NT = K_DIM / BK;           // 128
    for (int t = 0; t < NT; ++t) {
        const int buf = t & 1;
        if (t + 1 < NT) {
            load_tiles((t + 1) * BK, buf ^ 1);
            cp_commit();
            cp_wait<1>();
        } else {
            cp_wait<0>();
        }
        __syncthreads();

        const float* A0 = &As[buf * BM * PAD + (wm * 64 + g) * PAD];
        const float* B0 = &Bs[buf * BM * PAD + (wn * 32 + g) * PAD];

        #pragma unroll
        for (int kk = 0; kk < BK; kk += 8) {
            uint32_t a[4][4], b[4][2];
            #pragma unroll
            for (int mt = 0; mt < 4; mt++) {
                const float* p = A0 + mt * 16 * PAD + kk + tig;
                a[mt][0] = __float_as_uint(p[0]);
                a[mt][1] = __float_as_uint(p[8 * PAD]);
                a[mt][2] = __float_as_uint(p[4]);
                a[mt][3] = __float_as_uint(p[8 * PAD + 4]);
            }
            #pragma unroll
            for (int nt = 0; nt < 4; nt++) {
                const float* p = B0 + nt * 8 * PAD + kk + tig;
                b[nt][0] = __float_as_uint(p[0]);
                b[nt][1] = __float_as_uint(p[4]);
            }
            #pragma unroll
            for (int mt = 0; mt < 4; mt++)
                #pragma unroll
                for (int nt = 0; nt < 4; nt++)
                    mma_tf32(acc[mt][nt], a[mt], b[nt]);
        }
        __syncthreads();
    }

    // epilogue: c0,c1 at (row g, cols 2*tig, 2*tig+1); c2,c3 at row g+8
    #pragma unroll
    for (int mt = 0; mt < 4; mt++) {
        int m0 = bM + wm * 64 + mt * 16 + g;
        #pragma unroll
        for (int nt = 0; nt < 4; nt++) {
            int n0 = bN + wn * 32 + nt * 8 + tig * 2;
            float2 lo = make_float2(acc[mt][nt][0], acc[mt][nt][1]);
            float2 hi = make_float2(acc[mt][nt][2], acc[mt][nt][3]);
            *reinterpret_cast<float2*>(&out[(size_t)m0 * N_DIM + n0])        = lo;
            *reinterpret_cast<float2*>(&out[(size_t)(m0 + 8) * N_DIM + n0])  = hi;
        }
    }
}

// ---------------------------------------------------------------------------
// launch
// ---------------------------------------------------------------------------
extern "C" void kernel_launch(void* const* d_in, const int* in_sizes, int n_in,
                              void* d_out, int out_size) {
    const float* x      = (const float*)d_in[0];
    const int*   qw     = (const int*)d_in[1];
    const float* scales = (const float*)d_in[2];
    const float* tables = (const float*)d_in[3];
    float*       out    = (float*)d_out;

    cudaFuncSetAttribute(gemm_tf32_kernel,
                         cudaFuncAttributeMaxDynamicSharedMemorySize, SMEM_BYTES);

    {   // x -> tf32(rna)
        size_t n4 = (size_t)M_DIM * K_DIM / 4;
        convert_x_kernel<<<(unsigned)(n4 / 256), 256>>>((const float4*)x);
    }
    {   // dequant -> tf32(rna)
        size_t n4 = (size_t)N_DIM * K_DIM / 4;
        dequant_kernel<<<(unsigned)(n4 / 256), 256>>>(qw, scales, tables);
    }
    dim3 grid(N_DIM / BN, M_DIM / BM);
    gemm_tf32_kernel<<<grid, THREADS, SMEM_BYTES>>>(out);
}

// round 4
// speedup vs baseline: 2.4940x; 2.4940x over previous
#include <cuda_runtime.h>
#include <cuda_fp16.h>
#include <cstdint>
#include <cstddef>

// Problem dims (fixed)
#define M_DIM 4096
#define N_DIM 4096
#define K_DIM 4096
#define G_DIM 32            // K / 128 groups

// GEMM tiling: 128x128x64 CTA tile, 8 warps (2M x 4N), warp tile 64x32
#define BM 128
#define BN 128
#define BK 64               // 64 fp16 = 128 B per row = one SW128 swizzle atom
#define NT (K_DIM / BK)     // 64 k-iterations
#define STAGES 3
#define THREADS 256

#define STAGE_BYTES (BM * 128)              // 16 KB per operand per stage
#define B_OFF (STAGES * STAGE_BYTES)        // B region base
#define SMEM_REQ (2 * STAGES * STAGE_BYTES + 1024)   // 96 KB + align slack

// Scratch (allocation banned; __device__ globals are the sanctioned workaround)
__device__ __half g_X[(size_t)M_DIM * K_DIM];
__device__ __half g_W[(size_t)N_DIM * K_DIM];

// ---------------------------------------------------------------------------
// helpers
// ---------------------------------------------------------------------------
__device__ __forceinline__ uint32_t smem_u32(const void* p) {
    uint32_t a;
    asm("{ .reg .u64 t; cvta.to.shared.u64 t, %1; cvt.u32.u64 %0, t; }" : "=r"(a) : "l"(p));
    return a;
}
__device__ __forceinline__ void cp_async16(uint32_t dst, const void* src) {
    asm volatile("cp.async.cg.shared.global [%0], [%1], 16;\n" :: "r"(dst), "l"(src));
}
__device__ __forceinline__ void cp_commit() { asm volatile("cp.async.commit_group;\n"); }
template <int N>
__device__ __forceinline__ void cp_wait() { asm volatile("cp.async.wait_group %0;\n" :: "n"(N)); }

__device__ __forceinline__ void ldsm_x4(uint32_t* r, uint32_t addr) {
    asm volatile("ldmatrix.sync.aligned.m8n8.x4.shared.b16 {%0,%1,%2,%3}, [%4];"
                 : "=r"(r[0]), "=r"(r[1]), "=r"(r[2]), "=r"(r[3]) : "r"(addr));
}
__device__ __forceinline__ void mma_f16(float* c, const uint32_t* a, const uint32_t* b) {
    asm volatile(
        "mma.sync.aligned.m16n8k16.row.col.f32.f16.f16.f32 "
        "{%0,%1,%2,%3}, {%4,%5,%6,%7}, {%8,%9}, {%0,%1,%2,%3};\n"
        : "+f"(c[0]), "+f"(c[1]), "+f"(c[2]), "+f"(c[3])
        : "r"(a[0]), "r"(a[1]), "r"(a[2]), "r"(a[3]), "r"(b[0]), "r"(b[1]));
}

// SW128 swizzle on a 128B-row tile with 1024B-aligned base: chunk' = chunk ^ (row&7)
#define SWZ128(o) ((o) ^ (((o) >> 3) & 0x70))

// ---------------------------------------------------------------------------
// prologue 1: x (fp32) -> g_X (fp16)
// ---------------------------------------------------------------------------
__global__ void convert_x_kernel(const float4* __restrict__ x) {
    size_t i = (size_t)blockIdx.x * blockDim.x + threadIdx.x;   // 8 elems/thread
    float4 a = x[2 * i], b = x[2 * i + 1];
    __half2 p0 = __floats2half2_rn(a.x, a.y);
    __half2 p1 = __floats2half2_rn(a.z, a.w);
    __half2 p2 = __floats2half2_rn(b.x, b.y);
    __half2 p3 = __floats2half2_rn(b.z, b.w);
    uint4 o;
    o.x = *reinterpret_cast<uint32_t*>(&p0);
    o.y = *reinterpret_cast<uint32_t*>(&p1);
    o.z = *reinterpret_cast<uint32_t*>(&p2);
    o.w = *reinterpret_cast<uint32_t*>(&p3);
    reinterpret_cast<uint4*>(g_X)[i] = o;
}

// ---------------------------------------------------------------------------
// prologue 2: LUT dequant -> g_W (fp16):  W[n,k] = h(tables[q]*scales[n,k/128])
// ---------------------------------------------------------------------------
__global__ void dequant_kernel(const int4* __restrict__ qw,
                               const float* __restrict__ scales,
                               const float* __restrict__ tables) {
    __shared__ float t[16];
    if (threadIdx.x < 16) t[threadIdx.x] = tables[threadIdx.x];
    __syncthreads();
    size_t i = (size_t)blockIdx.x * blockDim.x + threadIdx.x;   // 8 elems/thread
    int4 q0 = qw[2 * i], q1 = qw[2 * i + 1];
    size_t e0 = i << 3;
    int n = (int)(e0 >> 12);
    int k = (int)(e0 & 4095);
    float s = scales[n * G_DIM + (k >> 7)];      // constant across the 8 elems
    __half2 p0 = __floats2half2_rn(t[q0.x] * s, t[q0.y] * s);
    __half2 p1 = __floats2half2_rn(t[q0.z] * s, t[q0.w] * s);
    __half2 p2 = __floats2half2_rn(t[q1.x] * s, t[q1.y] * s);
    __half2 p3 = __floats2half2_rn(t[q1.z] * s, t[q1.w] * s);
    uint4 o;
    o.x = *reinterpret_cast<uint32_t*>(&p0);
    o.y = *reinterpret_cast<uint32_t*>(&p1);
    o.z = *reinterpret_cast<uint32_t*>(&p2);
    o.w = *reinterpret_cast<uint32_t*>(&p3);
    reinterpret_cast<uint4*>(g_W)[i] = o;
}

// ---------------------------------------------------------------------------
// main GEMM: fp16 mma.sync m16n8k16 + ldmatrix + SW128 swizzle + 3-stage cp.async
// ---------------------------------------------------------------------------
__global__ void __launch_bounds__(THREADS, 2)
gemm_f16_mma(float* __restrict__ out) {
    extern __shared__ char dsmem[];
    const uint32_t base = (smem_u32(dsmem) + 1023) & ~1023u;

    const int tid  = threadIdx.x;
    const int warp = tid >> 5;
    const int lane = tid & 31;
    const int wm   = warp >> 2;          // 0..1
    const int wn   = warp & 3;           // 0..3
    const int q    = lane >> 3;          // ldmatrix quad 0..3
    const int t7   = lane & 7;

    const int bM = blockIdx.y * BM;
    const int bN = blockIdx.x * BN;
    const __half* gA = g_X + (size_t)bM * K_DIM;
    const __half* gB = g_W + (size_t)bN * K_DIM;

    float acc[4][4][4];
    #pragma unroll
    for (int i = 0; i < 4; i++)
        #pragma unroll
        for (int j = 0; j < 4; j++)
            #pragma unroll
            for (int r = 0; r < 4; r++) acc[i][j][r] = 0.f;

    // ldmatrix per-thread geometry
    // A quads: q0: rows+0 chunk lo | q1: rows+8 chunk lo | q2: rows+0 hi | q3: rows+8 hi
    const int aq = q >> 1;                            // A chunk offset (0/1)
    uint32_t a_off[4], a_xr[4];
    #pragma unroll
    for (int mt = 0; mt < 4; mt++) {
        int row = wm * 64 + mt * 16 + (q & 1) * 8 + t7;
        a_off[mt] = (uint32_t)row * 128;
        a_xr[mt]  = (uint32_t)(row & 7);
    }
    // B quads: q0: nt0 rows chunk lo | q1: nt0 hi | q2: nt1 rows lo | q3: nt1 hi
    const int bq = q & 1;                             // B chunk offset (0/1)
    uint32_t b_off[2], b_xr[2];
    #pragma unroll
    for (int p = 0; p < 2; p++) {
        int row = wn * 32 + p * 16 + (q >> 1) * 8 + t7;
        b_off[p] = (uint32_t)row * 128;
        b_xr[p]  = (uint32_t)(row & 7);
    }

    // global->shared tile loader: 128 rows x 128B per operand, SW128 dst
    auto load_tiles = [&](int iter, int buf) {
        const int k0 = iter * BK;
        const uint32_t As = base + buf * STAGE_BYTES;
        const uint32_t Bs = base + B_OFF + buf * STAGE_BYTES;
        #pragma unroll
        for (int j = 0; j < 4; j++) {
            int idx = tid + j * THREADS;
            int row = idx >> 3, cc = idx & 7;
            cp_async16(As + SWZ128((uint32_t)(row * 128 + cc * 16)),
                       gA + (size_t)row * K_DIM + k0 + cc * 8);
            cp_async16(Bs + SWZ128((uint32_t)(row * 128 + cc * 16)),
                       gB + (size_t)row * K_DIM + k0 + cc * 8);
        }
    };

    // preload stages 0..1
    load_tiles(0, 0); cp_commit();
    load_tiles(1, 1); cp_commit();

    int buf = 0;
    for (int t = 0; t < NT; ++t) {
        cp_wait<STAGES - 2>();
        __syncthreads();

        // prefetch t+2 into the buffer freed at iter t-1
        if (t + 2 < NT) {
            int nb = buf + 2; if (nb >= STAGES) nb -= STAGES;
            load_tiles(t + 2, nb);
        }
        cp_commit();                      // keep group count fixed

        const uint32_t As = base + buf * STAGE_BYTES;
        const uint32_t Bs = base + B_OFF + buf * STAGE_BYTES;

        #pragma unroll
        for (int s = 0; s < 4; s++) {     // 4 k-steps of K=16
            uint32_t a[4][4], b[4][2];
            #pragma unroll
            for (int mt = 0; mt < 4; mt++)
                ldsm_x4(a[mt], As + a_off[mt] + (((uint32_t)(2 * s + aq) ^ a_xr[mt]) << 4));
            #pragma unroll
            for (int p = 0; p < 2; p++) {
                uint32_t r[4];
                ldsm_x4(r, Bs + b_off[p] + (((uint32_t)(2 * s + bq) ^ b_xr[p]) << 4));
                b[2 * p][0] = r[0]; b[2 * p][1] = r[1];
                b[2 * p + 1][0] = r[2]; b[2 * p + 1][1] = r[3];
            }
            #pragma unroll
            for (int mt = 0; mt < 4; mt++)
                #pragma unroll
                for (int nt = 0; nt < 4; nt++)
                    mma_f16(acc[mt][nt], a[mt], b[nt]);
        }
        __syncthreads();
        if (++buf == STAGES) buf = 0;
    }

    // epilogue: c0,c1 -> (row g, cols 2c,2c+1); c2,c3 -> row g+8
    const int g = lane >> 2, c4 = lane & 3;
    #pragma unroll
    for (int mt = 0; mt < 4; mt++) {
        int m0 = bM + wm * 64 + mt * 16 + g;
        #pragma unroll
        for (int nt = 0; nt < 4; nt++) {
            int n0 = bN + wn * 32 + nt * 8 + c4 * 2;
            float2 lo = make_float2(acc[mt][nt][0], acc[mt][nt][1]);
            float2 hi = make_float2(acc[mt][nt][2], acc[mt][nt][3]);
            *reinterpret_cast<float2*>(&out[(size_t)m0 * N_DIM + n0])       = lo;
            *reinterpret_cast<float2*>(&out[(size_t)(m0 + 8) * N_DIM + n0]) = hi;
        }
    }
}

// ---------------------------------------------------------------------------
// launch
// ---------------------------------------------------------------------------
extern "C" void kernel_launch(void* const* d_in, const int* in_sizes, int n_in,
                              void* d_out, int out_size) {
    const float* x      = (const float*)d_in[0];
    const int*   qw     = (const int*)d_in[1];
    const float* scales = (const float*)d_in[2];
    const float* tables = (const float*)d_in[3];
    float*       out    = (float*)d_out;

    cudaFuncSetAttribute(gemm_f16_mma,
                         cudaFuncAttributeMaxDynamicSharedMemorySize, SMEM_REQ);

    convert_x_kernel<<<8192, 256>>>((const float4*)x);                 // 16M elems / 8
    dequant_kernel<<<8192, 256>>>((const int4*)qw, scales, tables);    // 16M elems / 8

    dim3 grid(N_DIM / BN, M_DIM / BM);   // (32, 32)
    gemm_f16_mma<<<grid, THREADS, SMEM_REQ>>>(out);
}